// round 2
// baseline (speedup 1.0000x reference)
#include <cuda_runtime.h>
#include <math.h>
#include <stddef.h>

// ---------------- problem constants ----------------
#define BB   2
#define SS   2048
#define DD   1024
#define HH   16
#define HDIM 64
#define DFFC 2048
#define BH   (BB*HH)        // 32
#define NTOK (BB*SS)        // 4096

#define MU_C   1.0f
#define K_C    3.0f
#define DT_C   0.02f
#define MIX_C  0.3f
// cos(0.1), sin(0.1)
#define CA_C   0.9950041652780258f
#define SA_C   0.09983341664682815f

// ---------------- scratch (device globals; no runtime alloc) ----------------
__device__ float g_A    [(size_t)BH * SS * SS];     // 512 MiB attention matrix
__device__ float g_xn   [(size_t)NTOK * DD];
__device__ float g_q    [(size_t)BH * SS * HDIM];
__device__ float g_kT   [(size_t)BH * HDIM * SS];
__device__ float g_ab   [(size_t)BH * SS * 128];    // [a | b]
__device__ float g_z    [(size_t)BH * SS * 128];    // [za | zb]
__device__ float g_d1   [(size_t)BH * SS * 128];    // [da1 | db1]
__device__ float g_abp  [(size_t)BH * SS * 128];    // predictor [ap | bp]
__device__ float g_attnv[(size_t)BH * SS * HDIM];
__device__ float g_mix  [(size_t)BH * SS * HDIM];
__device__ float g_x1   [(size_t)NTOK * DD];
__device__ float g_ff   [(size_t)NTOK * DFFC];

// ---------------- helpers ----------------
__device__ __forceinline__ float gelu_tanh(float x) {
    float x3 = x * x * x;
    float t  = tanhf(0.7978845608028654f * (x + 0.044715f * x3));
    return 0.5f * x * (1.0f + t);
}

// ---------------- LayerNorm: one block per row of 1024 ----------------
__global__ void ln_kernel(const float* __restrict__ x, const float* __restrict__ g,
                          const float* __restrict__ be, float* __restrict__ out)
{
    __shared__ float sh[8];
    size_t row = blockIdx.x;
    int tid = threadIdx.x, lane = tid & 31, wid = tid >> 5;
    float4 v = reinterpret_cast<const float4*>(x + row * DD)[tid];

    float s = v.x + v.y + v.z + v.w;
#pragma unroll
    for (int o = 16; o; o >>= 1) s += __shfl_xor_sync(0xffffffffu, s, o);
    if (lane == 0) sh[wid] = s;
    __syncthreads();
    float tot = 0.f;
#pragma unroll
    for (int i = 0; i < 8; i++) tot += sh[i];
    float mean = tot * (1.0f / DD);

    float dx = v.x - mean, dy = v.y - mean, dz = v.z - mean, dw = v.w - mean;
    float s2 = dx*dx + dy*dy + dz*dz + dw*dw;
#pragma unroll
    for (int o = 16; o; o >>= 1) s2 += __shfl_xor_sync(0xffffffffu, s2, o);
    __syncthreads();
    if (lane == 0) sh[wid] = s2;
    __syncthreads();
    float tot2 = 0.f;
#pragma unroll
    for (int i = 0; i < 8; i++) tot2 += sh[i];
    float rstd = rsqrtf(tot2 * (1.0f / DD) + 1e-5f);

    float4 gv = reinterpret_cast<const float4*>(g)[tid];
    float4 bv = reinterpret_cast<const float4*>(be)[tid];
    float4 o4;
    o4.x = dx * rstd * gv.x + bv.x;
    o4.y = dy * rstd * gv.y + bv.y;
    o4.z = dz * rstd * gv.z + bv.z;
    o4.w = dw * rstd * gv.w + bv.w;
    reinterpret_cast<float4*>(out + row * DD)[tid] = o4;
}

// ---------------- QKV projection per (b,h), 64-row tiles ----------------
// q[bh,s,e], kT[bh,e,s] (pre-transposed for the score GEMM),
// ab[bh,s,0:64]=v (a0), ab[bh,s,64:128]=0 (b0)
__global__ void qkv_kernel(const float* __restrict__ xn,
                           const float* __restrict__ Wq, const float* __restrict__ Wk,
                           const float* __restrict__ Wv,
                           float* __restrict__ q, float* __restrict__ kT,
                           float* __restrict__ ab)
{
    __shared__ float sx[64][65];
    __shared__ float sw[64][65];
    int bh = blockIdx.y, b = bh >> 4, h = bh & 15;
    int s0 = blockIdx.x * 64;
    int tid = threadIdx.x;

    for (int idx = tid; idx < 4096; idx += 256) {
        int r = idx >> 6, d = idx & 63;
        sx[r][d] = xn[((size_t)(b * SS + s0 + r)) * DD + h * 64 + d];
    }
    int e = tid & 63, rq = tid >> 6;
    const float* Ws[3] = { Wq + h * 4096, Wk + h * 4096, Wv + h * 4096 };

    for (int w = 0; w < 3; w++) {
        __syncthreads();
        for (int idx = tid; idx < 4096; idx += 256)
            sw[idx >> 6][idx & 63] = Ws[w][idx];
        __syncthreads();
#pragma unroll
        for (int i = 0; i < 16; i++) {
            int r = rq * 16 + i;
            float acc = 0.f;
#pragma unroll
            for (int d = 0; d < 64; d++) acc = fmaf(sx[r][d], sw[d][e], acc);
            size_t srow = (size_t)bh * SS + s0 + r;
            if (w == 0)      q[srow * 64 + e] = acc;
            else if (w == 1) kT[((size_t)bh * 64 + e) * SS + s0 + r] = acc;
            else { ab[srow * 128 + e] = acc; ab[srow * 128 + 64 + e] = 0.f; }
        }
    }
}

// ---------------- generic batched SGEMM C = A@B (+bias)(+addsrc)(gelu) ----------------
// 128x128 tile, BK=16, 8x8 per thread, 256 threads. All M,N used here are
// multiples of 128 and K a multiple of 16, so no bounds checks needed.
__global__ __launch_bounds__(256, 2) void sgemm_kernel(
    const float* __restrict__ A, const float* __restrict__ Bm, float* __restrict__ C,
    int K, int lda, int ldb, int ldc,
    long long sA, long long sB, long long sC,
    const float* __restrict__ addsrc, const float* __restrict__ bias, int do_gelu)
{
    A  += (long long)blockIdx.z * sA;
    Bm += (long long)blockIdx.z * sB;
    C  += (long long)blockIdx.z * sC;

    __shared__ float As[16][132];   // A tile transposed [k][m]
    __shared__ float Bs[16][132];   // B tile natural    [k][n]

    int tid = threadIdx.x;
    int tx = tid & 15, ty = tid >> 4;
    int row0 = blockIdx.y * 128, col0 = blockIdx.x * 128;
    float acc[8][8] = {};

    for (int k0 = 0; k0 < K; k0 += 16) {
#pragma unroll
        for (int i = 0; i < 2; i++) {
            int idx = tid + (i << 8);
            int r = idx >> 2;
            int kk = (idx & 3) << 2;
            float4 v = *reinterpret_cast<const float4*>(
                A + (long long)(row0 + r) * lda + k0 + kk);
            As[kk + 0][r] = v.x; As[kk + 1][r] = v.y;
            As[kk + 2][r] = v.z; As[kk + 3][r] = v.w;
        }
#pragma unroll
        for (int i = 0; i < 2; i++) {
            int idx = tid + (i << 8);
            int kk = idx >> 5;
            int c = (idx & 31) << 2;
            float4 v = *reinterpret_cast<const float4*>(
                Bm + (long long)(k0 + kk) * ldb + col0 + c);
            *reinterpret_cast<float4*>(&Bs[kk][c]) = v;
        }
        __syncthreads();
#pragma unroll
        for (int kk = 0; kk < 16; kk++) {
            float af[8], bf[8];
#pragma unroll
            for (int i = 0; i < 8; i++) af[i] = As[kk][(ty << 3) + i];
#pragma unroll
            for (int j = 0; j < 8; j++) bf[j] = Bs[kk][(tx << 3) + j];
#pragma unroll
            for (int i = 0; i < 8; i++)
#pragma unroll
                for (int j = 0; j < 8; j++)
                    acc[i][j] = fmaf(af[i], bf[j], acc[i][j]);
        }
        __syncthreads();
    }

#pragma unroll
    for (int i = 0; i < 8; i++) {
        long long r = row0 + (ty << 3) + i;
#pragma unroll
        for (int j = 0; j < 8; j++) {
            int c = col0 + (tx << 3) + j;
            float v = acc[i][j];
            if (bias)   v += bias[c];
            if (addsrc) v += addsrc[r * ldc + c];
            if (do_gelu) v = gelu_tanh(v);
            C[r * ldc + c] = v;
        }
    }
}

// ---------------- row softmax over A (with 1/sqrt(HD) scale) ----------------
__global__ void softmax_kernel(float* __restrict__ A)
{
    __shared__ float sh[8];
    size_t row = blockIdx.x;
    float* p = A + row * (size_t)SS;
    int tid = threadIdx.x, lane = tid & 31, wid = tid >> 5;

    float4 v0 = reinterpret_cast<float4*>(p)[tid];
    float4 v1 = reinterpret_cast<float4*>(p)[tid + 256];
    const float sc = 0.125f;
    v0.x *= sc; v0.y *= sc; v0.z *= sc; v0.w *= sc;
    v1.x *= sc; v1.y *= sc; v1.z *= sc; v1.w *= sc;

    float mx = fmaxf(fmaxf(fmaxf(v0.x, v0.y), fmaxf(v0.z, v0.w)),
                     fmaxf(fmaxf(v1.x, v1.y), fmaxf(v1.z, v1.w)));
#pragma unroll
    for (int o = 16; o; o >>= 1) mx = fmaxf(mx, __shfl_xor_sync(0xffffffffu, mx, o));
    if (lane == 0) sh[wid] = mx;
    __syncthreads();
    float m = sh[0];
#pragma unroll
    for (int i = 1; i < 8; i++) m = fmaxf(m, sh[i]);

    v0.x = expf(v0.x - m); v0.y = expf(v0.y - m);
    v0.z = expf(v0.z - m); v0.w = expf(v0.w - m);
    v1.x = expf(v1.x - m); v1.y = expf(v1.y - m);
    v1.z = expf(v1.z - m); v1.w = expf(v1.w - m);

    float s = v0.x + v0.y + v0.z + v0.w + v1.x + v1.y + v1.z + v1.w;
#pragma unroll
    for (int o = 16; o; o >>= 1) s += __shfl_xor_sync(0xffffffffu, s, o);
    __syncthreads();
    if (lane == 0) sh[wid] = s;
    __syncthreads();
    float tot = 0.f;
#pragma unroll
    for (int i = 0; i < 8; i++) tot += sh[i];
    float inv = 1.0f / tot;

    v0.x *= inv; v0.y *= inv; v0.z *= inv; v0.w *= inv;
    v1.x *= inv; v1.y *= inv; v1.z *= inv; v1.w *= inv;
    reinterpret_cast<float4*>(p)[tid]       = v0;
    reinterpret_cast<float4*>(p)[tid + 256] = v1;
}

// ---------------- ODE elementwise: first f eval + Heun predictor ----------------
__global__ void ode_ew1(const float* __restrict__ ab, const float* __restrict__ z,
                        const float* __restrict__ omega, float* __restrict__ d1,
                        float* __restrict__ abp, float* __restrict__ attnv, int save_attnv)
{
    size_t i = (size_t)blockIdx.x * blockDim.x + threadIdx.x;   // over BH*SS*64
    size_t base = (i >> 6) * 128 + (i & 63);
    int h = (int)((i >> 17) & 15);          // SS*64 = 2^17 elems per (b,h)
    float om = omega[(h << 6) + (int)(i & 63)];

    float a = ab[base], b = ab[base + 64];
    float za = z[base], zb = z[base + 64];
    if (save_attnv) attnv[i] = za;          // attn_v == A@v on the first eval

    float r2 = a * a + b * b;
    float ra = za * CA_C + zb * SA_C;
    float rb = zb * CA_C - za * SA_C;
    float da = (MU_C - r2) * a - om * b + K_C * (ra - a);
    float db = (MU_C - r2) * b + om * a + K_C * (rb - b);
    d1[base] = da; d1[base + 64] = db;
    abp[base] = a + DT_C * da;
    abp[base + 64] = b + DT_C * db;
}

// ---------------- ODE elementwise: second f eval + Heun corrector ----------------
// On the last step also emits mixed = MIX*attn_v + (1-MIX)*a_new.
__global__ void ode_ew2(float* __restrict__ ab, const float* __restrict__ abp,
                        const float* __restrict__ z, const float* __restrict__ omega,
                        const float* __restrict__ d1,
                        const float* __restrict__ attnv, float* __restrict__ mixed,
                        int emit_mixed)
{
    size_t i = (size_t)blockIdx.x * blockDim.x + threadIdx.x;
    size_t base = (i >> 6) * 128 + (i & 63);
    int h = (int)((i >> 17) & 15);
    float om = omega[(h << 6) + (int)(i & 63)];

    float a  = ab[base],  b  = ab[base + 64];
    float ap = abp[base], bp = abp[base + 64];
    float za = z[base],   zb = z[base + 64];
    float da1 = d1[base], db1 = d1[base + 64];

    float r2 = ap * ap + bp * bp;
    float ra = za * CA_C + zb * SA_C;
    float rb = zb * CA_C - za * SA_C;
    float da2 = (MU_C - r2) * ap - om * bp + K_C * (ra - ap);
    float db2 = (MU_C - r2) * bp + om * ap + K_C * (rb - bp);
    float an = a + 0.5f * DT_C * (da1 + da2);
    float bn = b + 0.5f * DT_C * (db1 + db2);
    ab[base]      = an;
    ab[base + 64] = bn;
    if (emit_mixed)
        mixed[i] = MIX_C * attnv[i] + (1.0f - MIX_C) * an;
}

// ---------------- head_out = mixed @ Wo[h]; x1 = x + scatter(head_out) ----------------
__global__ void headout_kernel(const float* __restrict__ mix, const float* __restrict__ Wo,
                               const float* __restrict__ x, float* __restrict__ x1)
{
    __shared__ float sx[64][65];
    __shared__ float sw[64][65];
    int bh = blockIdx.y, b = bh >> 4, h = bh & 15;
    int s0 = blockIdx.x * 64;
    int tid = threadIdx.x;

    for (int idx = tid; idx < 4096; idx += 256) {
        int r = idx >> 6, d = idx & 63;
        sx[r][d] = mix[((size_t)bh * SS + s0 + r) * 64 + d];
        sw[r][d] = Wo[h * 4096 + idx];
    }
    __syncthreads();
    int e = tid & 63, rq = tid >> 6;
#pragma unroll
    for (int i = 0; i < 16; i++) {
        int r = rq * 16 + i;
        float acc = 0.f;
#pragma unroll
        for (int d = 0; d < 64; d++) acc = fmaf(sx[r][d], sw[d][e], acc);
        size_t o = ((size_t)(b * SS + s0 + r)) * DD + h * 64 + e;
        x1[o] = x[o] + acc;
    }
}

// ---------------- host side ----------------
static void sgemm(const float* A, const float* Bm, float* C, int M, int N, int K,
                  int lda, int ldb, int ldc, long long sA, long long sB, long long sC,
                  int batch, const float* addsrc, const float* bias, int gelu)
{
    dim3 g(N / 128, M / 128, batch), blk(256);
    sgemm_kernel<<<g, blk>>>(A, Bm, C, K, lda, ldb, ldc, sA, sB, sC, addsrc, bias, gelu);
}

extern "C" void kernel_launch(void* const* d_in, const int* in_sizes, int n_in,
                              void* d_out, int out_size)
{
    const float* x   = (const float*)d_in[0];
    const float* Wq  = (const float*)d_in[1];
    const float* Wk  = (const float*)d_in[2];
    const float* Wv  = (const float*)d_in[3];
    const float* Wo  = (const float*)d_in[4];
    const float* om  = (const float*)d_in[5];
    const float* g1  = (const float*)d_in[6];
    const float* be1 = (const float*)d_in[7];
    const float* g2  = (const float*)d_in[8];
    const float* be2 = (const float*)d_in[9];
    const float* W1  = (const float*)d_in[10];
    const float* bf1 = (const float*)d_in[11];
    const float* W2  = (const float*)d_in[12];
    const float* bf2 = (const float*)d_in[13];
    float* out = (float*)d_out;
    (void)in_sizes; (void)n_in; (void)out_size;

    float *A_, *xn, *q, *kT, *ab, *z, *d1, *abp, *attnv, *mixb, *x1, *ff;
    cudaGetSymbolAddress((void**)&A_,    g_A);
    cudaGetSymbolAddress((void**)&xn,    g_xn);
    cudaGetSymbolAddress((void**)&q,     g_q);
    cudaGetSymbolAddress((void**)&kT,    g_kT);
    cudaGetSymbolAddress((void**)&ab,    g_ab);
    cudaGetSymbolAddress((void**)&z,     g_z);
    cudaGetSymbolAddress((void**)&d1,    g_d1);
    cudaGetSymbolAddress((void**)&abp,   g_abp);
    cudaGetSymbolAddress((void**)&attnv, g_attnv);
    cudaGetSymbolAddress((void**)&mixb,  g_mix);
    cudaGetSymbolAddress((void**)&x1,    g_x1);
    cudaGetSymbolAddress((void**)&ff,    g_ff);

    const long long sQ  = (long long)SS * 64;
    const long long sKT = (long long)64 * SS;
    const long long sAA = (long long)SS * SS;
    const long long sAB = (long long)SS * 128;

    // 1. LN(x) -> xn
    ln_kernel<<<NTOK, 256>>>(x, g1, be1, xn);
    // 2. q, kT, v(->ab a-half, b-half=0)
    qkv_kernel<<<dim3(SS / 64, BH), 256>>>(xn, Wq, Wk, Wv, q, kT, ab);
    // 3. raw scores: A = q @ k^T (scale applied in softmax)
    sgemm(q, kT, A_, SS, SS, 64, 64, SS, SS, sQ, sKT, sAA, BH, nullptr, nullptr, 0);
    // 4. softmax rows
    softmax_kernel<<<BH * SS, 256>>>(A_);
    // 5. Heun integration, 5 steps; first eval's za doubles as attn_v;
    //    last corrector emits mixed.
    int ew_blocks = (BH * SS * 64) / 256;
    for (int st = 0; st < 5; st++) {
        sgemm(A_, ab,  z, SS, 128, SS, SS, 128, 128, sAA, sAB, sAB, BH, nullptr, nullptr, 0);
        ode_ew1<<<ew_blocks, 256>>>(ab, z, om, d1, abp, attnv, st == 0 ? 1 : 0);
        sgemm(A_, abp, z, SS, 128, SS, SS, 128, 128, sAA, sAB, sAB, BH, nullptr, nullptr, 0);
        ode_ew2<<<ew_blocks, 256>>>(ab, abp, z, om, d1, attnv, mixb, st == 4 ? 1 : 0);
    }
    // 6. head projection + residual -> x1
    headout_kernel<<<dim3(SS / 64, BH), 256>>>(mixb, Wo, x, x1);
    // 7. LN(x1) -> xn (reuse)
    ln_kernel<<<NTOK, 256>>>(x1, g2, be2, xn);
    // 8. FFN1: gelu(xn @ W1 + bf1) -> ff
    sgemm(xn, W1, ff, NTOK, DFFC, DD, DD, DFFC, DFFC, 0, 0, 0, 1, nullptr, bf1, 1);
    // 9. FFN2: out = x1 + ff @ W2 + bf2
    sgemm(ff, W2, out, NTOK, DD, DFFC, DFFC, DD, DD, 0, 0, 0, 1, x1, bf2, 0);
}

// round 4
// speedup vs baseline: 1.8905x; 1.8905x over previous
#include <cuda_runtime.h>
#include <cuda_bf16.h>
#include <math.h>
#include <stddef.h>
#include <stdint.h>

// ---------------- problem constants ----------------
#define BB   2
#define SS   2048
#define DD   1024
#define HH   16
#define HDIM 64
#define DFFC 2048
#define BH   (BB*HH)        // 32
#define NTOK (BB*SS)        // 4096

#define MU_C   1.0f
#define K_C    3.0f
#define DT_C   0.02f
#define MIX_C  0.3f
#define CA_C   0.9950041652780258f
#define SA_C   0.09983341664682815f

// ---------------- scratch (device globals; no runtime alloc) ----------------
__device__ float g_A    [(size_t)BH * SS * SS];          // 512 MiB fp32 attention
__device__ __nv_bfloat16 g_Ahi[(size_t)BH * SS * SS];    // 256 MiB
__device__ __nv_bfloat16 g_Alo[(size_t)BH * SS * SS];    // 256 MiB
__device__ float g_xn   [(size_t)NTOK * DD];
__device__ float g_q    [(size_t)BH * SS * HDIM];
__device__ float g_kT   [(size_t)BH * HDIM * SS];
__device__ float g_ab   [(size_t)BH * SS * 128];         // [a | b] fp32
__device__ float g_z    [(size_t)BH * SS * 128];         // [za | zb]
__device__ float g_d1   [(size_t)BH * SS * 128];
__device__ float g_abp  [(size_t)BH * SS * 128];
__device__ __nv_bfloat16 g_abThi[(size_t)BH * 128 * SS]; // [c][t] split of ab
__device__ __nv_bfloat16 g_abTlo[(size_t)BH * 128 * SS];
__device__ __nv_bfloat16 g_pThi [(size_t)BH * 128 * SS]; // [c][t] split of abp
__device__ __nv_bfloat16 g_pTlo [(size_t)BH * 128 * SS];
__device__ float g_attnv[(size_t)BH * SS * HDIM];
__device__ float g_mix  [(size_t)BH * SS * HDIM];
__device__ float g_x1   [(size_t)NTOK * DD];
__device__ float g_ff   [(size_t)NTOK * DFFC];

// ---------------- low-level helpers (sm_100 baseline ISA only) ----------------
__device__ __forceinline__ uint32_t smem_u32(const void* p) {
    uint32_t a;
    asm("{ .reg .u64 t; cvta.to.shared.u64 t, %1; cvt.u32.u64 %0, t; }" : "=r"(a) : "l"(p));
    return a;
}
__device__ __forceinline__ void cp16(uint32_t s, const void* g) {
    asm volatile("cp.async.cg.shared.global [%0], [%1], 16;" :: "r"(s), "l"(g));
}
__device__ __forceinline__ void cp_commit() {
    asm volatile("cp.async.commit_group;" ::: "memory");
}
template <int N>
__device__ __forceinline__ void cp_wait() {
    asm volatile("cp.async.wait_group %0;" :: "n"(N) : "memory");
}
__device__ __forceinline__ void ldm_x4(uint32_t* r, uint32_t addr) {
    asm volatile("ldmatrix.sync.aligned.m8n8.x4.shared.b16 {%0,%1,%2,%3}, [%4];"
        : "=r"(r[0]), "=r"(r[1]), "=r"(r[2]), "=r"(r[3]) : "r"(addr));
}
__device__ __forceinline__ void ldm_x2(uint32_t* r, uint32_t addr) {
    asm volatile("ldmatrix.sync.aligned.m8n8.x2.shared.b16 {%0,%1}, [%2];"
        : "=r"(r[0]), "=r"(r[1]) : "r"(addr));
}
__device__ __forceinline__ void mma_bf16(float* c, const uint32_t* a, const uint32_t* b) {
    asm volatile("mma.sync.aligned.m16n8k16.row.col.f32.bf16.bf16.f32 "
        "{%0,%1,%2,%3}, {%4,%5,%6,%7}, {%8,%9}, {%0,%1,%2,%3};"
        : "+f"(c[0]), "+f"(c[1]), "+f"(c[2]), "+f"(c[3])
        : "r"(a[0]), "r"(a[1]), "r"(a[2]), "r"(a[3]), "r"(b[0]), "r"(b[1]));
}

// ---------------- resgemm: z[bh,s,0:128] = A[bh] @ X[bh]^T, 3-product bf16 ----------------
// Block: 128x128 tile, BK=64, 256 threads (8 warps as 2x4), double-buffered cp.async.
// A operand [m][k] K-major; X operand [n][k] K-major (pre-transposed by splitT).
#define RSTRIDE 72                       // bf16 per smem row (64 + 8 pad)
#define ROPND   (128 * RSTRIDE * 2)      // 18432 bytes per operand tile
#define RSMEM   (2 * 2 * ROPND)          // 73728 bytes (2 buffers x (A,X))

__global__ void __launch_bounds__(256, 1)
resgemm_kernel(const __nv_bfloat16* __restrict__ Ahi,
               const __nv_bfloat16* __restrict__ Alo,
               const __nv_bfloat16* __restrict__ Xhi,
               const __nv_bfloat16* __restrict__ Xlo,
               float* __restrict__ z)
{
    extern __shared__ char smem[];
    const uint32_t sb = smem_u32(smem);
    const int tid = threadIdx.x;
    const int lane = tid & 31, w = tid >> 5;
    const int wm = w >> 2, wn = w & 3;       // warp tile: rows wm*64, cols wn*32
    const int m0 = blockIdx.x * 128;
    const int bh = blockIdx.y;

    const __nv_bfloat16* Ah = Ahi + (size_t)bh * SS * SS + (size_t)m0 * SS;
    const __nv_bfloat16* Al = Alo + (size_t)bh * SS * SS + (size_t)m0 * SS;
    const __nv_bfloat16* Xh = Xhi + (size_t)bh * 128 * SS;
    const __nv_bfloat16* Xl = Xlo + (size_t)bh * 128 * SS;

    // per-thread load geometry: 4 chunks of 16B per operand per tile
    const int lrow = tid >> 3;           // 0..31 (+ j*32)
    const int lcol = (tid & 7) * 8;      // bf16 offset within row (x8 = 16B)

    float acc[4][4][4];
#pragma unroll
    for (int i = 0; i < 4; i++)
#pragma unroll
        for (int j = 0; j < 4; j++)
#pragma unroll
            for (int r = 0; r < 4; r++) acc[i][j][r] = 0.f;

    // issue loads for virtual iteration i into buffer b
    auto issue = [&](int i, int b) {
        int seg = i >> 5;
        int k0 = (i & 31) << 6;
        const __nv_bfloat16* Ag = ((seg == 2) ? Al : Ah) + k0 + lcol;
        const __nv_bfloat16* Xg = ((seg == 1) ? Xl : Xh) + k0 + lcol;
        uint32_t sA = sb + b * 2 * ROPND + lrow * (RSTRIDE * 2) + lcol * 2;
        uint32_t sX = sA + ROPND;
#pragma unroll
        for (int j = 0; j < 4; j++) {
            cp16(sA + j * 32 * (RSTRIDE * 2), Ag + (size_t)(lrow + j * 32) * SS);
            cp16(sX + j * 32 * (RSTRIDE * 2), Xg + (size_t)(lrow + j * 32) * SS);
        }
        cp_commit();
    };

    // compute one BK=64 tile from buffer b
    auto compute = [&](int b) {
        uint32_t sA = sb + b * 2 * ROPND;
        uint32_t sX = sA + ROPND;
#pragma unroll
        for (int k16 = 0; k16 < 4; k16++) {
            uint32_t afr[4][4], bfr[4][2];
#pragma unroll
            for (int ms = 0; ms < 4; ms++) {
                int row = wm * 64 + ms * 16 + (lane & 15);
                int kc = k16 * 16 + (lane >> 4) * 8;
                ldm_x4(afr[ms], sA + (row * RSTRIDE + kc) * 2);
            }
#pragma unroll
            for (int ns = 0; ns < 4; ns++) {
                int row = wn * 32 + ns * 8 + (lane & 7);
                int kc = k16 * 16 + (((lane & 15) >> 3)) * 8;
                ldm_x2(bfr[ns], sX + (row * RSTRIDE + kc) * 2);
            }
#pragma unroll
            for (int ms = 0; ms < 4; ms++)
#pragma unroll
                for (int ns = 0; ns < 4; ns++)
                    mma_bf16(acc[ms][ns], afr[ms], bfr[ns]);
        }
    };

    const int NIT = 96;                  // 3 segments x 32 chunks
    issue(0, 0);
#pragma unroll 1
    for (int i = 0; i < NIT - 1; i++) {
        issue(i + 1, (i + 1) & 1);
        cp_wait<1>();
        __syncthreads();
        compute(i & 1);
        __syncthreads();
    }
    cp_wait<0>();
    __syncthreads();
    compute((NIT - 1) & 1);

    // epilogue: write z fp32
    float* zb = z + ((size_t)bh * SS + m0) * 128;
#pragma unroll
    for (int ms = 0; ms < 4; ms++) {
#pragma unroll
        for (int ns = 0; ns < 4; ns++) {
            int r0 = wm * 64 + ms * 16 + (lane >> 2);
            int c0 = wn * 32 + ns * 8 + (lane & 3) * 2;
            *reinterpret_cast<float2*>(zb + (size_t)r0 * 128 + c0) =
                make_float2(acc[ms][ns][0], acc[ms][ns][1]);
            *reinterpret_cast<float2*>(zb + (size_t)(r0 + 8) * 128 + c0) =
                make_float2(acc[ms][ns][2], acc[ms][ns][3]);
        }
    }
}

// ---------------- split A (fp32 -> bf16 hi + lo) ----------------
__global__ void splitA_kernel(const float* __restrict__ A,
                              __nv_bfloat16* __restrict__ hi, __nv_bfloat16* __restrict__ lo)
{
    size_t i = ((size_t)blockIdx.x * blockDim.x + threadIdx.x) * 4;
    float4 v = *reinterpret_cast<const float4*>(A + i);
    __nv_bfloat162 h0, h1, l0, l1;
    h0.x = __float2bfloat16(v.x); h0.y = __float2bfloat16(v.y);
    h1.x = __float2bfloat16(v.z); h1.y = __float2bfloat16(v.w);
    l0.x = __float2bfloat16(v.x - __bfloat162float(h0.x));
    l0.y = __float2bfloat16(v.y - __bfloat162float(h0.y));
    l1.x = __float2bfloat16(v.z - __bfloat162float(h1.x));
    l1.y = __float2bfloat16(v.w - __bfloat162float(h1.y));
    *reinterpret_cast<__nv_bfloat162*>(hi + i)     = h0;
    *reinterpret_cast<__nv_bfloat162*>(hi + i + 2) = h1;
    *reinterpret_cast<__nv_bfloat162*>(lo + i)     = l0;
    *reinterpret_cast<__nv_bfloat162*>(lo + i + 2) = l1;
}

// ---------------- transpose+split: [bh][t][c:128] fp32 -> [bh][c:128][t] bf16 hi/lo ----------------
__global__ void splitT_kernel(const float* __restrict__ src,
                              __nv_bfloat16* __restrict__ hi, __nv_bfloat16* __restrict__ lo)
{
    __shared__ float tile[32][33];
    int bh = blockIdx.z;
    int t0 = blockIdx.x * 32, c0 = blockIdx.y * 32;
    int tx = threadIdx.x, ty = threadIdx.y;   // 32 x 8
    const float* s = src + ((size_t)bh * SS + t0) * 128 + c0;
#pragma unroll
    for (int i = 0; i < 4; i++)
        tile[ty + i * 8][tx] = s[(size_t)(ty + i * 8) * 128 + tx];
    __syncthreads();
    size_t ob = ((size_t)bh * 128 + c0) * SS + t0;
#pragma unroll
    for (int i = 0; i < 4; i++) {
        int cl = ty + i * 8;
        float f = tile[tx][cl];
        __nv_bfloat16 h = __float2bfloat16(f);
        hi[ob + (size_t)cl * SS + tx] = h;
        lo[ob + (size_t)cl * SS + tx] = __float2bfloat16(f - __bfloat162float(h));
    }
}

// ---------------- helpers ----------------
__device__ __forceinline__ float gelu_tanh(float x) {
    float x3 = x * x * x;
    float t  = tanhf(0.7978845608028654f * (x + 0.044715f * x3));
    return 0.5f * x * (1.0f + t);
}

// ---------------- LayerNorm ----------------
__global__ void ln_kernel(const float* __restrict__ x, const float* __restrict__ g,
                          const float* __restrict__ be, float* __restrict__ out)
{
    __shared__ float sh[8];
    size_t row = blockIdx.x;
    int tid = threadIdx.x, lane = tid & 31, wid = tid >> 5;
    float4 v = reinterpret_cast<const float4*>(x + row * DD)[tid];

    float s = v.x + v.y + v.z + v.w;
#pragma unroll
    for (int o = 16; o; o >>= 1) s += __shfl_xor_sync(0xffffffffu, s, o);
    if (lane == 0) sh[wid] = s;
    __syncthreads();
    float tot = 0.f;
#pragma unroll
    for (int i = 0; i < 8; i++) tot += sh[i];
    float mean = tot * (1.0f / DD);

    float dx = v.x - mean, dy = v.y - mean, dz = v.z - mean, dw = v.w - mean;
    float s2 = dx*dx + dy*dy + dz*dz + dw*dw;
#pragma unroll
    for (int o = 16; o; o >>= 1) s2 += __shfl_xor_sync(0xffffffffu, s2, o);
    __syncthreads();
    if (lane == 0) sh[wid] = s2;
    __syncthreads();
    float tot2 = 0.f;
#pragma unroll
    for (int i = 0; i < 8; i++) tot2 += sh[i];
    float rstd = rsqrtf(tot2 * (1.0f / DD) + 1e-5f);

    float4 gv = reinterpret_cast<const float4*>(g)[tid];
    float4 bv = reinterpret_cast<const float4*>(be)[tid];
    float4 o4;
    o4.x = dx * rstd * gv.x + bv.x;
    o4.y = dy * rstd * gv.y + bv.y;
    o4.z = dz * rstd * gv.z + bv.z;
    o4.w = dw * rstd * gv.w + bv.w;
    reinterpret_cast<float4*>(out + row * DD)[tid] = o4;
}

// ---------------- QKV projection ----------------
__global__ void qkv_kernel(const float* __restrict__ xn,
                           const float* __restrict__ Wq, const float* __restrict__ Wk,
                           const float* __restrict__ Wv,
                           float* __restrict__ q, float* __restrict__ kT,
                           float* __restrict__ ab)
{
    __shared__ float sx[64][65];
    __shared__ float sw[64][65];
    int bh = blockIdx.y, b = bh >> 4, h = bh & 15;
    int s0 = blockIdx.x * 64;
    int tid = threadIdx.x;

    for (int idx = tid; idx < 4096; idx += 256) {
        int r = idx >> 6, d = idx & 63;
        sx[r][d] = xn[((size_t)(b * SS + s0 + r)) * DD + h * 64 + d];
    }
    int e = tid & 63, rq = tid >> 6;
    const float* Ws[3] = { Wq + h * 4096, Wk + h * 4096, Wv + h * 4096 };

    for (int w = 0; w < 3; w++) {
        __syncthreads();
        for (int idx = tid; idx < 4096; idx += 256)
            sw[idx >> 6][idx & 63] = Ws[w][idx];
        __syncthreads();
#pragma unroll
        for (int i = 0; i < 16; i++) {
            int r = rq * 16 + i;
            float acc = 0.f;
#pragma unroll
            for (int d = 0; d < 64; d++) acc = fmaf(sx[r][d], sw[d][e], acc);
            size_t srow = (size_t)bh * SS + s0 + r;
            if (w == 0)      q[srow * 64 + e] = acc;
            else if (w == 1) kT[((size_t)bh * 64 + e) * SS + s0 + r] = acc;
            else { ab[srow * 128 + e] = acc; ab[srow * 128 + 64 + e] = 0.f; }
        }
    }
}

// ---------------- generic batched fp32 SGEMM (scores + FFN) ----------------
__global__ __launch_bounds__(256, 2) void sgemm_kernel(
    const float* __restrict__ A, const float* __restrict__ Bm, float* __restrict__ C,
    int K, int lda, int ldb, int ldc,
    long long sA, long long sB, long long sC,
    const float* __restrict__ addsrc, const float* __restrict__ bias, int do_gelu)
{
    A  += (long long)blockIdx.z * sA;
    Bm += (long long)blockIdx.z * sB;
    C  += (long long)blockIdx.z * sC;

    __shared__ float As[16][132];
    __shared__ float Bs[16][132];

    int tid = threadIdx.x;
    int tx = tid & 15, ty = tid >> 4;
    int row0 = blockIdx.y * 128, col0 = blockIdx.x * 128;
    float acc[8][8] = {};

    for (int k0 = 0; k0 < K; k0 += 16) {
#pragma unroll
        for (int i = 0; i < 2; i++) {
            int idx = tid + (i << 8);
            int r = idx >> 2;
            int kk = (idx & 3) << 2;
            float4 v = *reinterpret_cast<const float4*>(
                A + (long long)(row0 + r) * lda + k0 + kk);
            As[kk + 0][r] = v.x; As[kk + 1][r] = v.y;
            As[kk + 2][r] = v.z; As[kk + 3][r] = v.w;
        }
#pragma unroll
        for (int i = 0; i < 2; i++) {
            int idx = tid + (i << 8);
            int kk = idx >> 5;
            int c = (idx & 31) << 2;
            float4 v = *reinterpret_cast<const float4*>(
                Bm + (long long)(k0 + kk) * ldb + col0 + c);
            *reinterpret_cast<float4*>(&Bs[kk][c]) = v;
        }
        __syncthreads();
#pragma unroll
        for (int kk = 0; kk < 16; kk++) {
            float af[8], bf[8];
#pragma unroll
            for (int i = 0; i < 8; i++) af[i] = As[kk][(ty << 3) + i];
#pragma unroll
            for (int j = 0; j < 8; j++) bf[j] = Bs[kk][(tx << 3) + j];
#pragma unroll
            for (int i = 0; i < 8; i++)
#pragma unroll
                for (int j = 0; j < 8; j++)
                    acc[i][j] = fmaf(af[i], bf[j], acc[i][j]);
        }
        __syncthreads();
    }

#pragma unroll
    for (int i = 0; i < 8; i++) {
        long long r = row0 + (ty << 3) + i;
#pragma unroll
        for (int j = 0; j < 8; j++) {
            int c = col0 + (tx << 3) + j;
            float v = acc[i][j];
            if (bias)   v += bias[c];
            if (addsrc) v += addsrc[r * ldc + c];
            if (do_gelu) v = gelu_tanh(v);
            C[r * ldc + c] = v;
        }
    }
}

// ---------------- row softmax ----------------
__global__ void softmax_kernel(float* __restrict__ A)
{
    __shared__ float sh[8];
    size_t row = blockIdx.x;
    float* p = A + row * (size_t)SS;
    int tid = threadIdx.x, lane = tid & 31, wid = tid >> 5;

    float4 v0 = reinterpret_cast<float4*>(p)[tid];
    float4 v1 = reinterpret_cast<float4*>(p)[tid + 256];
    const float sc = 0.125f;
    v0.x *= sc; v0.y *= sc; v0.z *= sc; v0.w *= sc;
    v1.x *= sc; v1.y *= sc; v1.z *= sc; v1.w *= sc;

    float mx = fmaxf(fmaxf(fmaxf(v0.x, v0.y), fmaxf(v0.z, v0.w)),
                     fmaxf(fmaxf(v1.x, v1.y), fmaxf(v1.z, v1.w)));
#pragma unroll
    for (int o = 16; o; o >>= 1) mx = fmaxf(mx, __shfl_xor_sync(0xffffffffu, mx, o));
    if (lane == 0) sh[wid] = mx;
    __syncthreads();
    float m = sh[0];
#pragma unroll
    for (int i = 1; i < 8; i++) m = fmaxf(m, sh[i]);

    v0.x = expf(v0.x - m); v0.y = expf(v0.y - m);
    v0.z = expf(v0.z - m); v0.w = expf(v0.w - m);
    v1.x = expf(v1.x - m); v1.y = expf(v1.y - m);
    v1.z = expf(v1.z - m); v1.w = expf(v1.w - m);

    float s = v0.x + v0.y + v0.z + v0.w + v1.x + v1.y + v1.z + v1.w;
#pragma unroll
    for (int o = 16; o; o >>= 1) s += __shfl_xor_sync(0xffffffffu, s, o);
    __syncthreads();
    if (lane == 0) sh[wid] = s;
    __syncthreads();
    float tot = 0.f;
#pragma unroll
    for (int i = 0; i < 8; i++) tot += sh[i];
    float inv = 1.0f / tot;

    v0.x *= inv; v0.y *= inv; v0.z *= inv; v0.w *= inv;
    v1.x *= inv; v1.y *= inv; v1.z *= inv; v1.w *= inv;
    reinterpret_cast<float4*>(p)[tid]       = v0;
    reinterpret_cast<float4*>(p)[tid + 256] = v1;
}

// ---------------- ODE elementwise ----------------
__global__ void ode_ew1(const float* __restrict__ ab, const float* __restrict__ z,
                        const float* __restrict__ omega, float* __restrict__ d1,
                        float* __restrict__ abp, float* __restrict__ attnv, int save_attnv)
{
    size_t i = (size_t)blockIdx.x * blockDim.x + threadIdx.x;
    size_t base = (i >> 6) * 128 + (i & 63);
    int h = (int)((i >> 17) & 15);
    float om = omega[(h << 6) + (int)(i & 63)];

    float a = ab[base], b = ab[base + 64];
    float za = z[base], zb = z[base + 64];
    if (save_attnv) attnv[i] = za;

    float r2 = a * a + b * b;
    float ra = za * CA_C + zb * SA_C;
    float rb = zb * CA_C - za * SA_C;
    float da = (MU_C - r2) * a - om * b + K_C * (ra - a);
    float db = (MU_C - r2) * b + om * a + K_C * (rb - b);
    d1[base] = da; d1[base + 64] = db;
    abp[base] = a + DT_C * da;
    abp[base + 64] = b + DT_C * db;
}

__global__ void ode_ew2(float* __restrict__ ab, const float* __restrict__ abp,
                        const float* __restrict__ z, const float* __restrict__ omega,
                        const float* __restrict__ d1,
                        const float* __restrict__ attnv, float* __restrict__ mixed,
                        int emit_mixed)
{
    size_t i = (size_t)blockIdx.x * blockDim.x + threadIdx.x;
    size_t base = (i >> 6) * 128 + (i & 63);
    int h = (int)((i >> 17) & 15);
    float om = omega[(h << 6) + (int)(i & 63)];

    float a  = ab[base],  b  = ab[base + 64];
    float ap = abp[base], bp = abp[base + 64];
    float za = z[base],   zb = z[base + 64];
    float da1 = d1[base], db1 = d1[base + 64];

    float r2 = ap * ap + bp * bp;
    float ra = za * CA_C + zb * SA_C;
    float rb = zb * CA_C - za * SA_C;
    float da2 = (MU_C - r2) * ap - om * bp + K_C * (ra - ap);
    float db2 = (MU_C - r2) * bp + om * ap + K_C * (rb - bp);
    float an = a + 0.5f * DT_C * (da1 + da2);
    float bn = b + 0.5f * DT_C * (db1 + db2);
    ab[base]      = an;
    ab[base + 64] = bn;
    if (emit_mixed)
        mixed[i] = MIX_C * attnv[i] + (1.0f - MIX_C) * an;
}

// ---------------- head projection + residual ----------------
__global__ void headout_kernel(const float* __restrict__ mix, const float* __restrict__ Wo,
                               const float* __restrict__ x, float* __restrict__ x1)
{
    __shared__ float sx[64][65];
    __shared__ float sw[64][65];
    int bh = blockIdx.y, b = bh >> 4, h = bh & 15;
    int s0 = blockIdx.x * 64;
    int tid = threadIdx.x;

    for (int idx = tid; idx < 4096; idx += 256) {
        int r = idx >> 6, d = idx & 63;
        sx[r][d] = mix[((size_t)bh * SS + s0 + r) * 64 + d];
        sw[r][d] = Wo[h * 4096 + idx];
    }
    __syncthreads();
    int e = tid & 63, rq = tid >> 6;
#pragma unroll
    for (int i = 0; i < 16; i++) {
        int r = rq * 16 + i;
        float acc = 0.f;
#pragma unroll
        for (int d = 0; d < 64; d++) acc = fmaf(sx[r][d], sw[d][e], acc);
        size_t o = ((size_t)(b * SS + s0 + r)) * DD + h * 64 + e;
        x1[o] = x[o] + acc;
    }
}

// ---------------- host side ----------------
static void sgemm(const float* A, const float* Bm, float* C, int M, int N, int K,
                  int lda, int ldb, int ldc, long long sA, long long sB, long long sC,
                  int batch, const float* addsrc, const float* bias, int gelu)
{
    dim3 g(N / 128, M / 128, batch), blk(256);
    sgemm_kernel<<<g, blk>>>(A, Bm, C, K, lda, ldb, ldc, sA, sB, sC, addsrc, bias, gelu);
}

extern "C" void kernel_launch(void* const* d_in, const int* in_sizes, int n_in,
                              void* d_out, int out_size)
{
    const float* x   = (const float*)d_in[0];
    const float* Wq  = (const float*)d_in[1];
    const float* Wk  = (const float*)d_in[2];
    const float* Wv  = (const float*)d_in[3];
    const float* Wo  = (const float*)d_in[4];
    const float* om  = (const float*)d_in[5];
    const float* g1  = (const float*)d_in[6];
    const float* be1 = (const float*)d_in[7];
    const float* g2  = (const float*)d_in[8];
    const float* be2 = (const float*)d_in[9];
    const float* W1  = (const float*)d_in[10];
    const float* bf1 = (const float*)d_in[11];
    const float* W2  = (const float*)d_in[12];
    const float* bf2 = (const float*)d_in[13];
    float* out = (float*)d_out;
    (void)in_sizes; (void)n_in; (void)out_size;

    float *A_, *xn, *q, *kT, *ab, *z, *d1, *abp, *attnv, *mixb, *x1, *ff;
    __nv_bfloat16 *Ahi, *Alo, *abThi, *abTlo, *pThi, *pTlo;
    cudaGetSymbolAddress((void**)&A_,    g_A);
    cudaGetSymbolAddress((void**)&Ahi,   g_Ahi);
    cudaGetSymbolAddress((void**)&Alo,   g_Alo);
    cudaGetSymbolAddress((void**)&xn,    g_xn);
    cudaGetSymbolAddress((void**)&q,     g_q);
    cudaGetSymbolAddress((void**)&kT,    g_kT);
    cudaGetSymbolAddress((void**)&ab,    g_ab);
    cudaGetSymbolAddress((void**)&z,     g_z);
    cudaGetSymbolAddress((void**)&d1,    g_d1);
    cudaGetSymbolAddress((void**)&abp,   g_abp);
    cudaGetSymbolAddress((void**)&abThi, g_abThi);
    cudaGetSymbolAddress((void**)&abTlo, g_abTlo);
    cudaGetSymbolAddress((void**)&pThi,  g_pThi);
    cudaGetSymbolAddress((void**)&pTlo,  g_pTlo);
    cudaGetSymbolAddress((void**)&attnv, g_attnv);
    cudaGetSymbolAddress((void**)&mixb,  g_mix);
    cudaGetSymbolAddress((void**)&x1,    g_x1);
    cudaGetSymbolAddress((void**)&ff,    g_ff);

    cudaFuncSetAttribute(resgemm_kernel,
                         cudaFuncAttributeMaxDynamicSharedMemorySize, RSMEM);

    const long long sQ  = (long long)SS * 64;
    const long long sKT = (long long)64 * SS;
    const long long sAA = (long long)SS * SS;

    dim3 gT(SS / 32, 128 / 32, BH), bT(32, 8);
    dim3 gR(SS / 128, BH);

    // 1. LN(x) -> xn
    ln_kernel<<<NTOK, 256>>>(x, g1, be1, xn);
    // 2. q, kT, v(->ab a-half, b-half=0)
    qkv_kernel<<<dim3(SS / 64, BH), 256>>>(xn, Wq, Wk, Wv, q, kT, ab);
    // 3. scores A = q @ kT (fp32 SIMT)
    sgemm(q, kT, A_, SS, SS, 64, 64, SS, SS, sQ, sKT, sAA, BH, nullptr, nullptr, 0);
    // 4. softmax rows
    softmax_kernel<<<BH * SS, 256>>>(A_);
    // 5. split A into bf16 hi/lo (once)
    splitA_kernel<<<(unsigned)((size_t)BH * SS * SS / 1024), 256>>>(A_, Ahi, Alo);
    // 6. initial transposed split of ab
    splitT_kernel<<<gT, bT>>>(ab, abThi, abTlo);
    // 7. Heun integration, 5 steps on tensor cores (mma.sync bf16 3-product)
    int ew_blocks = (BH * SS * 64) / 256;
    for (int st = 0; st < 5; st++) {
        resgemm_kernel<<<gR, 256, RSMEM>>>(Ahi, Alo, abThi, abTlo, z);
        ode_ew1<<<ew_blocks, 256>>>(ab, z, om, d1, abp, attnv, st == 0 ? 1 : 0);
        splitT_kernel<<<gT, bT>>>(abp, pThi, pTlo);
        resgemm_kernel<<<gR, 256, RSMEM>>>(Ahi, Alo, pThi, pTlo, z);
        ode_ew2<<<ew_blocks, 256>>>(ab, abp, z, om, d1, attnv, mixb, st == 4 ? 1 : 0);
        if (st < 4) splitT_kernel<<<gT, bT>>>(ab, abThi, abTlo);
    }
    // 8. head projection + residual -> x1
    headout_kernel<<<dim3(SS / 64, BH), 256>>>(mixb, Wo, x, x1);
    // 9. LN(x1) -> xn
    ln_kernel<<<NTOK, 256>>>(x1, g2, be2, xn);
    // 10. FFN1: gelu(xn @ W1 + bf1) -> ff
    sgemm(xn, W1, ff, NTOK, DFFC, DD, DD, DFFC, DFFC, 0, 0, 0, 1, nullptr, bf1, 1);
    // 11. FFN2: out = x1 + ff @ W2 + bf2
    sgemm(ff, W2, out, NTOK, DD, DFFC, DFFC, DD, DD, 0, 0, 0, 1, x1, bf2, 0);
}

// round 5
// speedup vs baseline: 2.2500x; 1.1902x over previous
#include <cuda_runtime.h>
#include <cuda_bf16.h>
#include <math.h>
#include <stddef.h>
#include <stdint.h>

// ---------------- problem constants ----------------
#define BB   2
#define SS   2048
#define DD   1024
#define HH   16
#define HDIM 64
#define DFFC 2048
#define BH   (BB*HH)        // 32
#define NTOK (BB*SS)        // 4096

#define MU_C   1.0f
#define K_C    3.0f
#define DT_C   0.02f
#define MIX_C  0.3f
#define CA_C   0.9950041652780258f
#define SA_C   0.09983341664682815f

// ---------------- scratch (device globals) ----------------
__device__ float g_S [(size_t)BH * SS * SS];             // raw scores fp32
__device__ __nv_bfloat16 g_Ahi[(size_t)BH * SS * SS];
__device__ __nv_bfloat16 g_Alo[(size_t)BH * SS * SS];
__device__ float g_xn  [(size_t)NTOK * DD];
__device__ __nv_bfloat16 g_xnhi[(size_t)NTOK * DD];
__device__ __nv_bfloat16 g_xnlo[(size_t)NTOK * DD];
__device__ __nv_bfloat16 g_qhi[(size_t)BH * SS * 64];
__device__ __nv_bfloat16 g_qlo[(size_t)BH * SS * 64];
__device__ __nv_bfloat16 g_khi[(size_t)BH * SS * 64];
__device__ __nv_bfloat16 g_klo[(size_t)BH * SS * 64];
__device__ float g_ab  [(size_t)BH * SS * 128];
__device__ float g_z   [(size_t)BH * SS * 128];
__device__ float g_d1  [(size_t)BH * SS * 128];
__device__ float g_abp [(size_t)BH * SS * 128];
__device__ __nv_bfloat16 g_abThi[(size_t)BH * SS * 128]; // [t][c] layout
__device__ __nv_bfloat16 g_abTlo[(size_t)BH * SS * 128];
__device__ __nv_bfloat16 g_pThi [(size_t)BH * SS * 128];
__device__ __nv_bfloat16 g_pTlo [(size_t)BH * SS * 128];
__device__ float g_attnv[(size_t)BH * SS * 64];
__device__ float g_mix  [(size_t)BH * SS * 64];
__device__ float g_x1   [(size_t)NTOK * DD];
__device__ __nv_bfloat16 g_ffhi[(size_t)NTOK * DFFC];
__device__ __nv_bfloat16 g_fflo[(size_t)NTOK * DFFC];
__device__ __nv_bfloat16 g_W1hi[(size_t)DD * DFFC];
__device__ __nv_bfloat16 g_W1lo[(size_t)DD * DFFC];
__device__ __nv_bfloat16 g_W2hi[(size_t)DFFC * DD];
__device__ __nv_bfloat16 g_W2lo[(size_t)DFFC * DD];

// ---------------- low-level helpers ----------------
__device__ __forceinline__ uint32_t smem_u32(const void* p) {
    uint32_t a;
    asm("{ .reg .u64 t; cvta.to.shared.u64 t, %1; cvt.u32.u64 %0, t; }" : "=r"(a) : "l"(p));
    return a;
}
__device__ __forceinline__ void cp16(uint32_t s, const void* g) {
    asm volatile("cp.async.cg.shared.global [%0], [%1], 16;" :: "r"(s), "l"(g));
}
__device__ __forceinline__ void cp_commit() {
    asm volatile("cp.async.commit_group;" ::: "memory");
}
template <int N>
__device__ __forceinline__ void cp_wait() {
    asm volatile("cp.async.wait_group %0;" :: "n"(N) : "memory");
}
__device__ __forceinline__ void ldm_x4(uint32_t* r, uint32_t addr) {
    asm volatile("ldmatrix.sync.aligned.m8n8.x4.shared.b16 {%0,%1,%2,%3}, [%4];"
        : "=r"(r[0]), "=r"(r[1]), "=r"(r[2]), "=r"(r[3]) : "r"(addr));
}
__device__ __forceinline__ void ldm_x4t(uint32_t* r, uint32_t addr) {
    asm volatile("ldmatrix.sync.aligned.m8n8.x4.trans.shared.b16 {%0,%1,%2,%3}, [%4];"
        : "=r"(r[0]), "=r"(r[1]), "=r"(r[2]), "=r"(r[3]) : "r"(addr));
}
__device__ __forceinline__ void mma_bf16(float* c, const uint32_t* a, const uint32_t* b) {
    asm volatile("mma.sync.aligned.m16n8k16.row.col.f32.bf16.bf16.f32 "
        "{%0,%1,%2,%3}, {%4,%5,%6,%7}, {%8,%9}, {%0,%1,%2,%3};"
        : "+f"(c[0]), "+f"(c[1]), "+f"(c[2]), "+f"(c[3])
        : "r"(a[0]), "r"(a[1]), "r"(a[2]), "r"(a[3]), "r"(b[0]), "r"(b[1]));
}
__device__ __forceinline__ float gelu_tanh(float x) {
    float x3 = x * x * x;
    float t  = tanhf(0.7978845608028654f * (x + 0.044715f * x3));
    return 0.5f * x * (1.0f + t);
}

// ---------------- unified 3-product bf16 HMMA GEMM ----------------
// C[M,N] = (Ahi+Alo)[M,K] @ (Bhi+Blo) with 3 products (HixHi + HixLo + LoxHi).
// A stored K-major [m][k] (lda). B: TRANSB ? [k][n] (ldb = n-stride, ldmatrix.trans)
//                                          : [n][k] (ldb = k-stride).
// Block tile 128x128, BK=64, 256 threads (8 warps, 2x4), 2-stage cp.async.
#define AST 72                 // A smem row stride (bf16)
#define BSTN 72                // B non-trans row stride
#define BSTT 136               // B trans row stride
#define OFF_AL 18432
#define OFF_BH 36864
#define OFF_BL 55296
#define STAGE_BYTES 73728
#define HSMEM (2 * STAGE_BYTES)

template<bool TRANSB>
__global__ void __launch_bounds__(256, 1)
hgemm_kernel(const __nv_bfloat16* __restrict__ Ahi, const __nv_bfloat16* __restrict__ Alo,
             const __nv_bfloat16* __restrict__ Bhi, const __nv_bfloat16* __restrict__ Blo,
             int K, int lda, int ldb, int ldc,
             long long sA, long long sB, long long sC,
             float* __restrict__ outF,
             __nv_bfloat16* __restrict__ outHi, __nv_bfloat16* __restrict__ outLo,
             const float* __restrict__ bias, const float* __restrict__ addsrc, int do_gelu)
{
    extern __shared__ char smem[];
    const uint32_t sb = smem_u32(smem);
    const int tid = threadIdx.x;
    const int lane = tid & 31, w = tid >> 5;
    const int wm = w >> 2, wn = w & 3;
    const int n0 = blockIdx.x * 128;
    const int m0 = blockIdx.y * 128;
    const long long bz = blockIdx.z;

    Ahi += bz * sA; Alo += bz * sA;
    Bhi += bz * sB; Blo += bz * sB;

    float acc[4][4][4];
#pragma unroll
    for (int i = 0; i < 4; i++)
#pragma unroll
        for (int j = 0; j < 4; j++)
#pragma unroll
            for (int r = 0; r < 4; r++) acc[i][j][r] = 0.f;

    auto issue = [&](int chunk, int buf) {
        const int k0 = chunk << 6;
        const uint32_t st = sb + buf * STAGE_BYTES;
        {   // A hi+lo: [128 m][64 k]
            const int row = tid >> 3, col = (tid & 7) * 8;
            const __nv_bfloat16* gH = Ahi + (size_t)(m0 + row) * lda + k0 + col;
            const __nv_bfloat16* gL = Alo + (size_t)(m0 + row) * lda + k0 + col;
            uint32_t s = st + (row * AST + col) * 2;
#pragma unroll
            for (int j = 0; j < 4; j++) {
                cp16(s + j * 32 * (AST * 2),          gH + (size_t)j * 32 * lda);
                cp16(s + OFF_AL + j * 32 * (AST * 2), gL + (size_t)j * 32 * lda);
            }
        }
        if (TRANSB) {   // B: [64 k][128 n]
            const int rk = tid >> 2, col = (tid & 3) * 8;
            const __nv_bfloat16* gH = Bhi + (size_t)(k0 + rk) * ldb + n0 + col;
            const __nv_bfloat16* gL = Blo + (size_t)(k0 + rk) * ldb + n0 + col;
            uint32_t s = st + OFF_BH + (rk * BSTT + col) * 2;
#pragma unroll
            for (int j = 0; j < 4; j++) {
                cp16(s + j * 64,                     gH + j * 32);
                cp16(s + (OFF_BL - OFF_BH) + j * 64, gL + j * 32);
            }
        } else {        // B: [128 n][64 k]
            const int rn = tid >> 3, col = (tid & 7) * 8;
            const __nv_bfloat16* gH = Bhi + (size_t)(n0 + rn) * ldb + k0 + col;
            const __nv_bfloat16* gL = Blo + (size_t)(n0 + rn) * ldb + k0 + col;
            uint32_t s = st + OFF_BH + (rn * BSTN + col) * 2;
#pragma unroll
            for (int j = 0; j < 4; j++) {
                cp16(s + j * 32 * (BSTN * 2),                     gH + (size_t)j * 32 * ldb);
                cp16(s + (OFF_BL - OFF_BH) + j * 32 * (BSTN * 2), gL + (size_t)j * 32 * ldb);
            }
        }
        cp_commit();
    };

    auto compute = [&](int buf) {
        const uint32_t st = sb + buf * STAGE_BYTES;
#pragma unroll
        for (int k16 = 0; k16 < 4; k16++) {
            uint32_t afrH[4][4], afrL[4][4], bfrH[4][2], bfrL[4][2];
#pragma unroll
            for (int ms = 0; ms < 4; ms++) {
                int row = wm * 64 + ms * 16 + (lane & 15);
                int col = k16 * 16 + (lane >> 4) * 8;
                ldm_x4(afrH[ms], st + (row * AST + col) * 2);
                ldm_x4(afrL[ms], st + OFF_AL + (row * AST + col) * 2);
            }
            if (TRANSB) {
                const int mat = lane >> 3, rr = lane & 7;
#pragma unroll
                for (int p = 0; p < 2; p++) {
                    int rk = k16 * 16 + (mat & 1) * 8 + rr;
                    int cn = wn * 32 + p * 16 + (mat >> 1) * 8;
                    ldm_x4t(&bfrH[p * 2][0], st + OFF_BH + (rk * BSTT + cn) * 2);
                    ldm_x4t(&bfrL[p * 2][0], st + OFF_BL + (rk * BSTT + cn) * 2);
                }
            } else {
                const int mat = lane >> 3, rr = lane & 7;
#pragma unroll
                for (int p = 0; p < 2; p++) {
                    int rn = wn * 32 + p * 16 + (mat >> 1) * 8 + rr;
                    int ck = k16 * 16 + (mat & 1) * 8;
                    ldm_x4(&bfrH[p * 2][0], st + OFF_BH + (rn * BSTN + ck) * 2);
                    ldm_x4(&bfrL[p * 2][0], st + OFF_BL + (rn * BSTN + ck) * 2);
                }
            }
#pragma unroll
            for (int ms = 0; ms < 4; ms++)
#pragma unroll
                for (int ns = 0; ns < 4; ns++) {
                    mma_bf16(acc[ms][ns], afrH[ms], bfrH[ns]);
                    mma_bf16(acc[ms][ns], afrH[ms], bfrL[ns]);
                    mma_bf16(acc[ms][ns], afrL[ms], bfrH[ns]);
                }
        }
    };

    const int nchunk = K >> 6;
    issue(0, 0);
#pragma unroll 1
    for (int i = 0; i < nchunk; i++) {
        if (i + 1 < nchunk) { issue(i + 1, (i + 1) & 1); cp_wait<1>(); }
        else                { cp_wait<0>(); }
        __syncthreads();
        compute(i & 1);
        __syncthreads();
    }

    // ---- epilogue ----
    const long long cb = bz * sC;
#pragma unroll
    for (int ms = 0; ms < 4; ms++) {
#pragma unroll
        for (int ns = 0; ns < 4; ns++) {
            int r0 = wm * 64 + ms * 16 + (lane >> 2);
            int c0 = n0 + wn * 32 + ns * 8 + (lane & 3) * 2;
#pragma unroll
            for (int half = 0; half < 2; half++) {
                long long r = m0 + r0 + half * 8;
                float vx = acc[ms][ns][half * 2 + 0];
                float vy = acc[ms][ns][half * 2 + 1];
                if (bias)   { vx += bias[c0]; vy += bias[c0 + 1]; }
                if (addsrc) {
                    float2 s = *reinterpret_cast<const float2*>(addsrc + r * ldc + c0);
                    vx += s.x; vy += s.y;
                }
                if (do_gelu) { vx = gelu_tanh(vx); vy = gelu_tanh(vy); }
                long long o = cb + r * ldc + c0;
                if (outF)
                    *reinterpret_cast<float2*>(outF + o) = make_float2(vx, vy);
                if (outHi) {
                    __nv_bfloat162 h, l;
                    h.x = __float2bfloat16(vx); h.y = __float2bfloat16(vy);
                    l.x = __float2bfloat16(vx - __bfloat162float(h.x));
                    l.y = __float2bfloat16(vy - __bfloat162float(h.y));
                    *reinterpret_cast<__nv_bfloat162*>(outHi + o) = h;
                    *reinterpret_cast<__nv_bfloat162*>(outLo + o) = l;
                }
            }
        }
    }
}

// ---------------- generic fp32 -> bf16 hi/lo split ----------------
__global__ void splitW_kernel(const float* __restrict__ A,
                              __nv_bfloat16* __restrict__ hi, __nv_bfloat16* __restrict__ lo)
{
    size_t i = ((size_t)blockIdx.x * blockDim.x + threadIdx.x) * 4;
    float4 v = *reinterpret_cast<const float4*>(A + i);
    __nv_bfloat162 h0, h1, l0, l1;
    h0.x = __float2bfloat16(v.x); h0.y = __float2bfloat16(v.y);
    h1.x = __float2bfloat16(v.z); h1.y = __float2bfloat16(v.w);
    l0.x = __float2bfloat16(v.x - __bfloat162float(h0.x));
    l0.y = __float2bfloat16(v.y - __bfloat162float(h0.y));
    l1.x = __float2bfloat16(v.z - __bfloat162float(h1.x));
    l1.y = __float2bfloat16(v.w - __bfloat162float(h1.y));
    *reinterpret_cast<__nv_bfloat162*>(hi + i)     = h0;
    *reinterpret_cast<__nv_bfloat162*>(hi + i + 2) = h1;
    *reinterpret_cast<__nv_bfloat162*>(lo + i)     = l0;
    *reinterpret_cast<__nv_bfloat162*>(lo + i + 2) = l1;
}

// ---------------- LayerNorm (optional bf16 hi/lo outputs) ----------------
__global__ void ln_kernel(const float* __restrict__ x, const float* __restrict__ g,
                          const float* __restrict__ be, float* __restrict__ out,
                          __nv_bfloat16* __restrict__ outHi, __nv_bfloat16* __restrict__ outLo)
{
    __shared__ float sh[8];
    size_t row = blockIdx.x;
    int tid = threadIdx.x, lane = tid & 31, wid = tid >> 5;
    float4 v = reinterpret_cast<const float4*>(x + row * DD)[tid];

    float s = v.x + v.y + v.z + v.w;
#pragma unroll
    for (int o = 16; o; o >>= 1) s += __shfl_xor_sync(0xffffffffu, s, o);
    if (lane == 0) sh[wid] = s;
    __syncthreads();
    float tot = 0.f;
#pragma unroll
    for (int i = 0; i < 8; i++) tot += sh[i];
    float mean = tot * (1.0f / DD);

    float dx = v.x - mean, dy = v.y - mean, dz = v.z - mean, dw = v.w - mean;
    float s2 = dx*dx + dy*dy + dz*dz + dw*dw;
#pragma unroll
    for (int o = 16; o; o >>= 1) s2 += __shfl_xor_sync(0xffffffffu, s2, o);
    __syncthreads();
    if (lane == 0) sh[wid] = s2;
    __syncthreads();
    float tot2 = 0.f;
#pragma unroll
    for (int i = 0; i < 8; i++) tot2 += sh[i];
    float rstd = rsqrtf(tot2 * (1.0f / DD) + 1e-5f);

    float4 gv = reinterpret_cast<const float4*>(g)[tid];
    float4 bv = reinterpret_cast<const float4*>(be)[tid];
    float4 o4;
    o4.x = dx * rstd * gv.x + bv.x;
    o4.y = dy * rstd * gv.y + bv.y;
    o4.z = dz * rstd * gv.z + bv.z;
    o4.w = dw * rstd * gv.w + bv.w;
    reinterpret_cast<float4*>(out + row * DD)[tid] = o4;
    if (outHi) {
        size_t i = row * DD + tid * 4;
        __nv_bfloat162 h0, h1, l0, l1;
        h0.x = __float2bfloat16(o4.x); h0.y = __float2bfloat16(o4.y);
        h1.x = __float2bfloat16(o4.z); h1.y = __float2bfloat16(o4.w);
        l0.x = __float2bfloat16(o4.x - __bfloat162float(h0.x));
        l0.y = __float2bfloat16(o4.y - __bfloat162float(h0.y));
        l1.x = __float2bfloat16(o4.z - __bfloat162float(h1.x));
        l1.y = __float2bfloat16(o4.w - __bfloat162float(h1.y));
        *reinterpret_cast<__nv_bfloat162*>(outHi + i)     = h0;
        *reinterpret_cast<__nv_bfloat162*>(outHi + i + 2) = h1;
        *reinterpret_cast<__nv_bfloat162*>(outLo + i)     = l0;
        *reinterpret_cast<__nv_bfloat162*>(outLo + i + 2) = l1;
    }
}

// ---------------- QKV projection -> bf16 hi/lo q,k + fp32/bf16 ab ----------------
__global__ void qkv_kernel(const float* __restrict__ xn,
                           const float* __restrict__ Wq, const float* __restrict__ Wk,
                           const float* __restrict__ Wv,
                           __nv_bfloat16* __restrict__ qhi, __nv_bfloat16* __restrict__ qlo,
                           __nv_bfloat16* __restrict__ khi, __nv_bfloat16* __restrict__ klo,
                           float* __restrict__ ab,
                           __nv_bfloat16* __restrict__ abThi, __nv_bfloat16* __restrict__ abTlo)
{
    __shared__ float sx[64][65];
    __shared__ float sw[64][65];
    int bh = blockIdx.y, b = bh >> 4, h = bh & 15;
    int s0 = blockIdx.x * 64;
    int tid = threadIdx.x;

    for (int idx = tid; idx < 4096; idx += 256) {
        int r = idx >> 6, d = idx & 63;
        sx[r][d] = xn[((size_t)(b * SS + s0 + r)) * DD + h * 64 + d];
    }
    int e = tid & 63, rq = tid >> 6;
    const float* Ws[3] = { Wq + h * 4096, Wk + h * 4096, Wv + h * 4096 };

    for (int w = 0; w < 3; w++) {
        __syncthreads();
        for (int idx = tid; idx < 4096; idx += 256)
            sw[idx >> 6][idx & 63] = Ws[w][idx];
        __syncthreads();
#pragma unroll
        for (int i = 0; i < 16; i++) {
            int r = rq * 16 + i;
            float acc = 0.f;
#pragma unroll
            for (int d = 0; d < 64; d++) acc = fmaf(sx[r][d], sw[d][e], acc);
            size_t srow = (size_t)bh * SS + s0 + r;
            __nv_bfloat16 hi = __float2bfloat16(acc);
            __nv_bfloat16 lo = __float2bfloat16(acc - __bfloat162float(hi));
            if (w == 0)      { qhi[srow * 64 + e] = hi; qlo[srow * 64 + e] = lo; }
            else if (w == 1) { khi[srow * 64 + e] = hi; klo[srow * 64 + e] = lo; }
            else {
                ab[srow * 128 + e] = acc; ab[srow * 128 + 64 + e] = 0.f;
                abThi[srow * 128 + e] = hi; abTlo[srow * 128 + e] = lo;
                abThi[srow * 128 + 64 + e] = __float2bfloat16(0.f);
                abTlo[srow * 128 + 64 + e] = __float2bfloat16(0.f);
            }
        }
    }
}

// ---------------- fused softmax + bf16 split (scores fp32 -> Ahi/Alo) ----------------
__global__ void softmax_split_kernel(const float* __restrict__ S,
                                     __nv_bfloat16* __restrict__ Ahi,
                                     __nv_bfloat16* __restrict__ Alo)
{
    __shared__ float sh[8];
    size_t row = blockIdx.x;
    const float* p = S + row * (size_t)SS;
    int tid = threadIdx.x, lane = tid & 31, wid = tid >> 5;

    float4 v0 = reinterpret_cast<const float4*>(p)[tid];
    float4 v1 = reinterpret_cast<const float4*>(p)[tid + 256];
    const float sc = 0.125f;
    v0.x *= sc; v0.y *= sc; v0.z *= sc; v0.w *= sc;
    v1.x *= sc; v1.y *= sc; v1.z *= sc; v1.w *= sc;

    float mx = fmaxf(fmaxf(fmaxf(v0.x, v0.y), fmaxf(v0.z, v0.w)),
                     fmaxf(fmaxf(v1.x, v1.y), fmaxf(v1.z, v1.w)));
#pragma unroll
    for (int o = 16; o; o >>= 1) mx = fmaxf(mx, __shfl_xor_sync(0xffffffffu, mx, o));
    if (lane == 0) sh[wid] = mx;
    __syncthreads();
    float m = sh[0];
#pragma unroll
    for (int i = 1; i < 8; i++) m = fmaxf(m, sh[i]);

    v0.x = expf(v0.x - m); v0.y = expf(v0.y - m);
    v0.z = expf(v0.z - m); v0.w = expf(v0.w - m);
    v1.x = expf(v1.x - m); v1.y = expf(v1.y - m);
    v1.z = expf(v1.z - m); v1.w = expf(v1.w - m);

    float s = v0.x + v0.y + v0.z + v0.w + v1.x + v1.y + v1.z + v1.w;
#pragma unroll
    for (int o = 16; o; o >>= 1) s += __shfl_xor_sync(0xffffffffu, s, o);
    __syncthreads();
    if (lane == 0) sh[wid] = s;
    __syncthreads();
    float tot = 0.f;
#pragma unroll
    for (int i = 0; i < 8; i++) tot += sh[i];
    float inv = 1.0f / tot;

    v0.x *= inv; v0.y *= inv; v0.z *= inv; v0.w *= inv;
    v1.x *= inv; v1.y *= inv; v1.z *= inv; v1.w *= inv;

    size_t ob = row * (size_t)SS;
    auto emit = [&](size_t off, float a, float b) {
        __nv_bfloat162 h, l;
        h.x = __float2bfloat16(a); h.y = __float2bfloat16(b);
        l.x = __float2bfloat16(a - __bfloat162float(h.x));
        l.y = __float2bfloat16(b - __bfloat162float(h.y));
        *reinterpret_cast<__nv_bfloat162*>(Ahi + ob + off) = h;
        *reinterpret_cast<__nv_bfloat162*>(Alo + ob + off) = l;
    };
    emit(tid * 4 + 0, v0.x, v0.y);
    emit(tid * 4 + 2, v0.z, v0.w);
    emit((tid + 256) * 4 + 0, v1.x, v1.y);
    emit((tid + 256) * 4 + 2, v1.z, v1.w);
}

// ---------------- ODE elementwise ----------------
__global__ void ode_ew1(const float* __restrict__ ab, const float* __restrict__ z,
                        const float* __restrict__ omega, float* __restrict__ d1,
                        float* __restrict__ abp,
                        __nv_bfloat16* __restrict__ pThi, __nv_bfloat16* __restrict__ pTlo,
                        float* __restrict__ attnv, int save_attnv)
{
    size_t i = (size_t)blockIdx.x * blockDim.x + threadIdx.x;
    size_t base = (i >> 6) * 128 + (i & 63);
    int h = (int)((i >> 17) & 15);
    float om = omega[(h << 6) + (int)(i & 63)];

    float a = ab[base], b = ab[base + 64];
    float za = z[base], zb = z[base + 64];
    if (save_attnv) attnv[i] = za;

    float r2 = a * a + b * b;
    float ra = za * CA_C + zb * SA_C;
    float rb = zb * CA_C - za * SA_C;
    float da = (MU_C - r2) * a - om * b + K_C * (ra - a);
    float db = (MU_C - r2) * b + om * a + K_C * (rb - b);
    d1[base] = da; d1[base + 64] = db;
    float ap = a + DT_C * da, bp = b + DT_C * db;
    abp[base] = ap; abp[base + 64] = bp;
    __nv_bfloat16 hA = __float2bfloat16(ap);
    __nv_bfloat16 hB = __float2bfloat16(bp);
    pThi[base]      = hA; pTlo[base]      = __float2bfloat16(ap - __bfloat162float(hA));
    pThi[base + 64] = hB; pTlo[base + 64] = __float2bfloat16(bp - __bfloat162float(hB));
}

__global__ void ode_ew2(float* __restrict__ ab, const float* __restrict__ abp,
                        const float* __restrict__ z, const float* __restrict__ omega,
                        const float* __restrict__ d1,
                        __nv_bfloat16* __restrict__ abThi, __nv_bfloat16* __restrict__ abTlo,
                        const float* __restrict__ attnv, float* __restrict__ mixed,
                        int emit_mixed)
{
    size_t i = (size_t)blockIdx.x * blockDim.x + threadIdx.x;
    size_t base = (i >> 6) * 128 + (i & 63);
    int h = (int)((i >> 17) & 15);
    float om = omega[(h << 6) + (int)(i & 63)];

    float a  = ab[base],  b  = ab[base + 64];
    float ap = abp[base], bp = abp[base + 64];
    float za = z[base],   zb = z[base + 64];
    float da1 = d1[base], db1 = d1[base + 64];

    float r2 = ap * ap + bp * bp;
    float ra = za * CA_C + zb * SA_C;
    float rb = zb * CA_C - za * SA_C;
    float da2 = (MU_C - r2) * ap - om * bp + K_C * (ra - ap);
    float db2 = (MU_C - r2) * bp + om * ap + K_C * (rb - bp);
    float an = a + 0.5f * DT_C * (da1 + da2);
    float bn = b + 0.5f * DT_C * (db1 + db2);
    ab[base]      = an;
    ab[base + 64] = bn;
    if (emit_mixed) {
        mixed[i] = MIX_C * attnv[i] + (1.0f - MIX_C) * an;
    } else {
        __nv_bfloat16 hA = __float2bfloat16(an);
        __nv_bfloat16 hB = __float2bfloat16(bn);
        abThi[base]      = hA; abTlo[base]      = __float2bfloat16(an - __bfloat162float(hA));
        abThi[base + 64] = hB; abTlo[base + 64] = __float2bfloat16(bn - __bfloat162float(hB));
    }
}

// ---------------- head projection + residual ----------------
__global__ void headout_kernel(const float* __restrict__ mix, const float* __restrict__ Wo,
                               const float* __restrict__ x, float* __restrict__ x1)
{
    __shared__ float sx[64][65];
    __shared__ float sw[64][65];
    int bh = blockIdx.y, b = bh >> 4, h = bh & 15;
    int s0 = blockIdx.x * 64;
    int tid = threadIdx.x;

    for (int idx = tid; idx < 4096; idx += 256) {
        int r = idx >> 6, d = idx & 63;
        sx[r][d] = mix[((size_t)bh * SS + s0 + r) * 64 + d];
        sw[r][d] = Wo[h * 4096 + idx];
    }
    __syncthreads();
    int e = tid & 63, rq = tid >> 6;
#pragma unroll
    for (int i = 0; i < 16; i++) {
        int r = rq * 16 + i;
        float acc = 0.f;
#pragma unroll
        for (int d = 0; d < 64; d++) acc = fmaf(sx[r][d], sw[d][e], acc);
        size_t o = ((size_t)(b * SS + s0 + r)) * DD + h * 64 + e;
        x1[o] = x[o] + acc;
    }
}

// ---------------- host side ----------------
extern "C" void kernel_launch(void* const* d_in, const int* in_sizes, int n_in,
                              void* d_out, int out_size)
{
    const float* x   = (const float*)d_in[0];
    const float* Wq  = (const float*)d_in[1];
    const float* Wk  = (const float*)d_in[2];
    const float* Wv  = (const float*)d_in[3];
    const float* Wo  = (const float*)d_in[4];
    const float* om  = (const float*)d_in[5];
    const float* g1  = (const float*)d_in[6];
    const float* be1 = (const float*)d_in[7];
    const float* g2  = (const float*)d_in[8];
    const float* be2 = (const float*)d_in[9];
    const float* W1  = (const float*)d_in[10];
    const float* bf1 = (const float*)d_in[11];
    const float* W2  = (const float*)d_in[12];
    const float* bf2 = (const float*)d_in[13];
    float* out = (float*)d_out;
    (void)in_sizes; (void)n_in; (void)out_size;

    float *S_, *xn, *ab, *z, *d1, *abp, *attnv, *mixb, *x1;
    __nv_bfloat16 *Ahi, *Alo, *xnhi, *xnlo, *qhi, *qlo, *khi, *klo;
    __nv_bfloat16 *abThi, *abTlo, *pThi, *pTlo, *ffhi, *fflo;
    __nv_bfloat16 *W1hi, *W1lo, *W2hi, *W2lo;
    cudaGetSymbolAddress((void**)&S_,    g_S);
    cudaGetSymbolAddress((void**)&Ahi,   g_Ahi);
    cudaGetSymbolAddress((void**)&Alo,   g_Alo);
    cudaGetSymbolAddress((void**)&xn,    g_xn);
    cudaGetSymbolAddress((void**)&xnhi,  g_xnhi);
    cudaGetSymbolAddress((void**)&xnlo,  g_xnlo);
    cudaGetSymbolAddress((void**)&qhi,   g_qhi);
    cudaGetSymbolAddress((void**)&qlo,   g_qlo);
    cudaGetSymbolAddress((void**)&khi,   g_khi);
    cudaGetSymbolAddress((void**)&klo,   g_klo);
    cudaGetSymbolAddress((void**)&ab,    g_ab);
    cudaGetSymbolAddress((void**)&z,     g_z);
    cudaGetSymbolAddress((void**)&d1,    g_d1);
    cudaGetSymbolAddress((void**)&abp,   g_abp);
    cudaGetSymbolAddress((void**)&abThi, g_abThi);
    cudaGetSymbolAddress((void**)&abTlo, g_abTlo);
    cudaGetSymbolAddress((void**)&pThi,  g_pThi);
    cudaGetSymbolAddress((void**)&pTlo,  g_pTlo);
    cudaGetSymbolAddress((void**)&attnv, g_attnv);
    cudaGetSymbolAddress((void**)&mixb,  g_mix);
    cudaGetSymbolAddress((void**)&x1,    g_x1);
    cudaGetSymbolAddress((void**)&ffhi,  g_ffhi);
    cudaGetSymbolAddress((void**)&fflo,  g_fflo);
    cudaGetSymbolAddress((void**)&W1hi,  g_W1hi);
    cudaGetSymbolAddress((void**)&W1lo,  g_W1lo);
    cudaGetSymbolAddress((void**)&W2hi,  g_W2hi);
    cudaGetSymbolAddress((void**)&W2lo,  g_W2lo);

    cudaFuncSetAttribute(hgemm_kernel<true>,
                         cudaFuncAttributeMaxDynamicSharedMemorySize, HSMEM);
    cudaFuncSetAttribute(hgemm_kernel<false>,
                         cudaFuncAttributeMaxDynamicSharedMemorySize, HSMEM);

    const long long sQK = (long long)SS * 64;
    const long long sAA = (long long)SS * SS;
    const long long sAB = (long long)SS * 128;

    // weight splits (independent)
    splitW_kernel<<<(unsigned)((size_t)DD * DFFC / 1024), 256>>>(W1, W1hi, W1lo);
    splitW_kernel<<<(unsigned)((size_t)DFFC * DD / 1024), 256>>>(W2, W2hi, W2lo);

    // 1. LN1
    ln_kernel<<<NTOK, 256>>>(x, g1, be1, xn, nullptr, nullptr);
    // 2. QKV -> bf16 splits + ab
    qkv_kernel<<<dim3(SS / 64, BH), 256>>>(xn, Wq, Wk, Wv, qhi, qlo, khi, klo,
                                           ab, abThi, abTlo);
    // 3. scores (HMMA 3-product): S = q @ k^T, B non-trans [t][d]
    hgemm_kernel<false><<<dim3(16, 16, BH), 256, HSMEM>>>(
        qhi, qlo, khi, klo, 64, 64, 64, SS, sQK, sQK, sAA,
        S_, nullptr, nullptr, nullptr, nullptr, 0);
    // 4. softmax + split -> Ahi/Alo
    softmax_split_kernel<<<BH * SS, 256>>>(S_, Ahi, Alo);
    // 5. Heun loop: z = A @ X (B trans [t][c])
    int ew_blocks = (BH * SS * 64) / 256;
    for (int st = 0; st < 5; st++) {
        hgemm_kernel<true><<<dim3(1, 16, BH), 256, HSMEM>>>(
            Ahi, Alo, abThi, abTlo, SS, SS, 128, 128, sAA, sAB, sAB,
            z, nullptr, nullptr, nullptr, nullptr, 0);
        ode_ew1<<<ew_blocks, 256>>>(ab, z, om, d1, abp, pThi, pTlo,
                                    attnv, st == 0 ? 1 : 0);
        hgemm_kernel<true><<<dim3(1, 16, BH), 256, HSMEM>>>(
            Ahi, Alo, pThi, pTlo, SS, SS, 128, 128, sAA, sAB, sAB,
            z, nullptr, nullptr, nullptr, nullptr, 0);
        ode_ew2<<<ew_blocks, 256>>>(ab, abp, z, om, d1, abThi, abTlo,
                                    attnv, mixb, st == 4 ? 1 : 0);
    }
    // 6. head projection + residual
    headout_kernel<<<dim3(SS / 64, BH), 256>>>(mixb, Wo, x, x1);
    // 7. LN2 -> fp32 + bf16 splits
    ln_kernel<<<NTOK, 256>>>(x1, g2, be2, xn, xnhi, xnlo);
    // 8. FFN1 (HMMA): gelu(xn @ W1 + bf1) -> ff hi/lo; W1 is [k][n] (trans)
    hgemm_kernel<true><<<dim3(16, 32, 1), 256, HSMEM>>>(
        xnhi, xnlo, W1hi, W1lo, DD, DD, DFFC, DFFC, 0, 0, 0,
        nullptr, ffhi, fflo, bf1, nullptr, 1);
    // 9. FFN2 (HMMA): out = x1 + ff @ W2 + bf2; W2 is [k][n] (trans)
    hgemm_kernel<true><<<dim3(8, 32, 1), 256, HSMEM>>>(
        ffhi, fflo, W2hi, W2lo, DFFC, DFFC, DD, DD, 0, 0, 0,
        out, nullptr, nullptr, bf2, x1, 0);
}